// round 13
// baseline (speedup 1.0000x reference)
#include <cuda_runtime.h>
#include <cuda_bf16.h>
#include <math.h>
#include <stdint.h>

#define Bn  8
#define Sn  1024
#define Dn  1024
#define Hn  16
#define DKn 64
#define QT  16
#define VSTR 260

// ---------------- scratch (device globals; no allocation allowed) -------------
__device__ __align__(256) float g_q  [Bn*Sn*Dn];
__device__ __align__(256) float g_k  [Bn*Sn*Dn];
__device__ __align__(256) float g_v  [Bn*Sn*Dn];
__device__ __align__(256) float g_ctx[Bn*Sn*Dn];
__device__ __align__(256) float g_res[Bn*Sn*Dn];
__device__ double g_part[Bn*32*2];
__device__ float g_stats[Bn*2];

// bf16 split scratch
__device__ __align__(256) __nv_bfloat16 g_xhi[Bn*Sn*Dn];
__device__ __align__(256) __nv_bfloat16 g_xlo[Bn*Sn*Dn];
__device__ __align__(256) __nv_bfloat16 g_chi[Bn*Sn*Dn];
__device__ __align__(256) __nv_bfloat16 g_clo[Bn*Sn*Dn];
__device__ __align__(256) __nv_bfloat16 g_bthi[3*Dn*Dn];   // qkv weights, Bt[n][k]
__device__ __align__(256) __nv_bfloat16 g_btlo[3*Dn*Dn];
__device__ __align__(256) __nv_bfloat16 g_wohi[Dn*Dn];     // wo^T, Bt[n][k]=WO[k][n]
__device__ __align__(256) __nv_bfloat16 g_wolo[Dn*Dn];

// ---------------- mma.sync helper (sm_80+ path, compiles on compute_103) ------
__device__ __forceinline__ void mma16816(float* c, const uint32_t* a, const uint32_t* b)
{
    asm volatile(
        "mma.sync.aligned.m16n8k16.row.col.f32.bf16.bf16.f32 "
        "{%0,%1,%2,%3}, {%4,%5,%6,%7}, {%8,%9}, {%0,%1,%2,%3};"
        : "+f"(c[0]), "+f"(c[1]), "+f"(c[2]), "+f"(c[3])
        : "r"(a[0]), "r"(a[1]), "r"(a[2]), "r"(a[3]), "r"(b[0]), "r"(b[1]));
}

// ======================== conversion kernels =================================
__global__ __launch_bounds__(256) void cvt_split_k(const float* __restrict__ xext, int which)
{
    const float* src = which ? g_ctx : xext;
    __nv_bfloat16* hi = which ? g_chi : g_xhi;
    __nv_bfloat16* lo = which ? g_clo : g_xlo;
    size_t i = ((size_t)blockIdx.x * 256 + threadIdx.x) * 4;
    float4 v = *(const float4*)(src + i);
    __nv_bfloat16 h0 = __float2bfloat16(v.x), l0 = __float2bfloat16(v.x - __bfloat162float(h0));
    __nv_bfloat16 h1 = __float2bfloat16(v.y), l1 = __float2bfloat16(v.y - __bfloat162float(h1));
    __nv_bfloat16 h2 = __float2bfloat16(v.z), l2 = __float2bfloat16(v.z - __bfloat162float(h2));
    __nv_bfloat16 h3 = __float2bfloat16(v.w), l3 = __float2bfloat16(v.w - __bfloat162float(h3));
    *(__nv_bfloat162*)(hi + i)     = __halves2bfloat162(h0, h1);
    *(__nv_bfloat162*)(hi + i + 2) = __halves2bfloat162(h2, h3);
    *(__nv_bfloat162*)(lo + i)     = __halves2bfloat162(l0, l1);
    *(__nv_bfloat162*)(lo + i + 2) = __halves2bfloat162(l2, l3);
}

// Bt_qkv[n][k] = Wsel[h][k][kk], n in [0,3072), h=(n%1024)/64, kk=n%64
__global__ __launch_bounds__(256) void cvt_wqkv_k(const float* __restrict__ WQ,
                                                  const float* __restrict__ WK,
                                                  const float* __restrict__ WV)
{
    size_t idx = (size_t)blockIdx.x * 256 + threadIdx.x;   // over 3072*1024
    int k = (int)(idx & 1023);
    int n = (int)(idx >> 10);
    int within = n & 1023, sel = n >> 10;
    const float* W = (sel == 0) ? WQ : (sel == 1 ? WK : WV);
    float w = W[(size_t)(within >> 6) * (Dn * DKn) + (size_t)k * DKn + (within & 63)];
    __nv_bfloat16 h = __float2bfloat16(w);
    g_bthi[idx] = h;
    g_btlo[idx] = __float2bfloat16(w - __bfloat162float(h));
}

// Bt_wo[n][k] = WO[k][n]  (tiled transpose + split)
__global__ __launch_bounds__(256) void cvt_wo_k(const float* __restrict__ WO)
{
    __shared__ float t[32][33];
    const int x = threadIdx.x, y = threadIdx.y;       // (32, 8)
    const int bx = blockIdx.x, by = blockIdx.y;
    #pragma unroll
    for (int i = 0; i < 4; i++)
        t[y + i * 8][x] = WO[(size_t)(by * 32 + y + i * 8) * Dn + bx * 32 + x];
    __syncthreads();
    #pragma unroll
    for (int i = 0; i < 4; i++) {
        float w = t[x][y + i * 8];
        __nv_bfloat16 h = __float2bfloat16(w);
        size_t o = (size_t)(bx * 32 + y + i * 8) * Dn + by * 32 + x;
        g_wohi[o] = h;
        g_wolo[o] = __float2bfloat16(w - __bfloat162float(h));
    }
}

// ======================== split-bf16 HMMA GEMM ===============================
// C[M x N] = A * Bt^T (Bt is [N][K] K-major). 128x128 tile, 8 warps (2x4),
// warp tile 64x32 (4x4 m16n8k16 frags), K-step 16, double-buffered SMEM.
// 3-pass split accumulate: Ahi*Bhi + Ahi*Blo + Alo*Bhi (fp32 accum).
// mode 0: qkv (OUT among g_q/g_k/g_v by n block); mode 1: out proj + residual.
__global__ __launch_bounds__(256, 1) void gemm_mma_k(const float* __restrict__ Xres, int mode)
{
    __shared__ __align__(16) __nv_bfloat16 sA[2][2][128 * 16];
    __shared__ __align__(16) __nv_bfloat16 sB[2][2][128 * 16];

    const int tid  = threadIdx.x;
    const int wid  = tid >> 5, lane = tid & 31;
    const int g    = lane >> 2, tg = lane & 3;
    const int m0   = blockIdx.y * 128;
    const int n0g  = blockIdx.x * 128;
    const int mo   = (wid >> 2) * 64;     // warp row offset in tile
    const int no   = (wid & 3) * 32;      // warp col offset in tile

    const __nv_bfloat16* Ahi = mode ? g_chi : g_xhi;
    const __nv_bfloat16* Alo = mode ? g_clo : g_xlo;
    const __nv_bfloat16* Bhi = mode ? g_wohi : g_bthi;
    const __nv_bfloat16* Blo = mode ? g_wolo : g_btlo;

    // loaders: thread covers one 8-bf16 segment; row = tid/2, seg = (tid&1)*8
    const int lrow = tid >> 1;
    const int lseg = (tid & 1) * 8;
    const __nv_bfloat16* pAhi = Ahi + (size_t)(m0 + lrow) * Dn + lseg;
    const __nv_bfloat16* pAlo = Alo + (size_t)(m0 + lrow) * Dn + lseg;
    const __nv_bfloat16* pBhi = Bhi + (size_t)(n0g + lrow) * Dn + lseg;
    const __nv_bfloat16* pBlo = Blo + (size_t)(n0g + lrow) * Dn + lseg;
    const int soff = lrow * 16 + lseg;

    float c[4][4][4];
    #pragma unroll
    for (int i = 0; i < 4; i++)
        #pragma unroll
        for (int j = 0; j < 4; j++)
            #pragma unroll
            for (int r = 0; r < 4; r++) c[i][j][r] = 0.f;

    // prologue: stage 0
    *(uint4*)&sA[0][0][soff] = *(const uint4*)pAhi;
    *(uint4*)&sA[0][1][soff] = *(const uint4*)pAlo;
    *(uint4*)&sB[0][0][soff] = *(const uint4*)pBhi;
    *(uint4*)&sB[0][1][soff] = *(const uint4*)pBlo;
    __syncthreads();

    const int NK = Dn / 16;   // 64
    for (int ks = 0; ks < NK; ks++) {
        const int cur = ks & 1;

        uint4 va, vb, vc, vd;
        if (ks < NK - 1) {
            const int k0 = (ks + 1) * 16;
            va = *(const uint4*)(pAhi + k0);
            vb = *(const uint4*)(pAlo + k0);
            vc = *(const uint4*)(pBhi + k0);
            vd = *(const uint4*)(pBlo + k0);
        }

        // load fragments
        uint32_t a[2][4][4];
        #pragma unroll
        for (int sp = 0; sp < 2; sp++) {
            const __nv_bfloat16* base = &sA[cur][sp][0];
            #pragma unroll
            for (int i = 0; i < 4; i++) {
                int r = (mo + i * 16 + g) * 16 + tg * 2;
                a[sp][i][0] = *(const uint32_t*)&base[r];
                a[sp][i][1] = *(const uint32_t*)&base[r + 8 * 16];
                a[sp][i][2] = *(const uint32_t*)&base[r + 8];
                a[sp][i][3] = *(const uint32_t*)&base[r + 8 * 16 + 8];
            }
        }
        uint32_t b[2][4][2];
        #pragma unroll
        for (int sp = 0; sp < 2; sp++) {
            const __nv_bfloat16* base = &sB[cur][sp][0];
            #pragma unroll
            for (int j = 0; j < 4; j++) {
                int r = (no + j * 8 + g) * 16 + tg * 2;
                b[sp][j][0] = *(const uint32_t*)&base[r];
                b[sp][j][1] = *(const uint32_t*)&base[r + 8];
            }
        }

        // 3-pass MMAs
        #pragma unroll
        for (int i = 0; i < 4; i++)
            #pragma unroll
            for (int j = 0; j < 4; j++) {
                mma16816(c[i][j], a[0][i], b[0][j]);   // hi*hi
                mma16816(c[i][j], a[0][i], b[1][j]);   // hi*lo
                mma16816(c[i][j], a[1][i], b[0][j]);   // lo*hi
            }

        if (ks < NK - 1) {
            const int nb = cur ^ 1;
            *(uint4*)&sA[nb][0][soff] = va;
            *(uint4*)&sA[nb][1][soff] = vb;
            *(uint4*)&sB[nb][0][soff] = vc;
            *(uint4*)&sB[nb][1][soff] = vd;
            __syncthreads();
        }
    }

    // epilogue
    float* OUT;
    int nbase;
    if (mode == 0) {
        int sel = n0g >> 10;
        OUT = (sel == 0) ? g_q : (sel == 1 ? g_k : g_v);
        nbase = n0g & 1023;
    } else {
        OUT = g_res;
        nbase = n0g;
    }

    #pragma unroll
    for (int i = 0; i < 4; i++) {
        #pragma unroll
        for (int j = 0; j < 4; j++) {
            const int r0  = m0 + mo + i * 16 + g;
            const int col = nbase + no + j * 8 + tg * 2;
            size_t o0 = (size_t)r0 * Dn + col;
            size_t o1 = (size_t)(r0 + 8) * Dn + col;
            float2 v0 = make_float2(c[i][j][0], c[i][j][1]);
            float2 v1 = make_float2(c[i][j][2], c[i][j][3]);
            if (mode == 1) {
                float2 x0 = *(const float2*)(Xres + o0);
                float2 x1 = *(const float2*)(Xres + o1);
                v0.x += x0.x; v0.y += x0.y;
                v1.x += x1.x; v1.y += x1.y;
            }
            *(float2*)(OUT + o0) = v0;
            *(float2*)(OUT + o1) = v1;
        }
    }
}

// ======================== attention (unchanged) ==============================
__global__ __launch_bounds__(256) void attn_k(const int* __restrict__ mask)
{
    extern __shared__ float sh[];
    float* sQ  = sh;
    float* sS  = sh + QT * 64;
    float* sVT = sS + QT * Sn;

    const int tid  = threadIdx.x;
    const int blk  = blockIdx.x;
    const int tile = blk % (Sn / QT);
    const int h    = (blk / (Sn / QT)) % Hn;
    const int b    = blk / ((Sn / QT) * Hn);
    const int s0   = tile * QT;

    {
        int j  = tid / 16;
        int d4 = (tid % 16) * 4;
        const float* qp = g_q + ((size_t)(b * Sn + s0 + j)) * Dn + h * DKn + d4;
        *(float4*)&sQ[j * 64 + d4] = *(const float4*)qp;
    }
    __syncthreads();

    const float scale = 0.125f;
    for (int c = 0; c < 4; c++) {
        const int t = c * 256 + tid;
        const float* kp = g_k + ((size_t)(b * Sn + t)) * Dn + h * DKn;
        float kreg[64];
        #pragma unroll
        for (int i = 0; i < 16; i++)
            *(float4*)&kreg[i * 4] = *(const float4*)(kp + i * 4);

        #pragma unroll
        for (int j = 0; j < QT; j++) {
            float s = 0.f;
            #pragma unroll
            for (int i = 0; i < 16; i++) {
                float4 qv = *(const float4*)&sQ[j * 64 + i * 4];
                s += qv.x * kreg[i * 4 + 0];
                s += qv.y * kreg[i * 4 + 1];
                s += qv.z * kreg[i * 4 + 2];
                s += qv.w * kreg[i * 4 + 3];
            }
            int m = mask[((size_t)(b * Sn) + (s0 + j)) * Sn + t];
            sS[j * Sn + t] = (m != 0) ? s * scale : -1e9f;
        }
    }
    __syncthreads();

    const int w = tid / 32, lane = tid % 32;
    #pragma unroll
    for (int rr = 0; rr < 2; rr++) {
        float* row = &sS[(w * 2 + rr) * Sn];
        float mx = -1e30f;
        #pragma unroll
        for (int i = 0; i < 32; i++) mx = fmaxf(mx, row[lane + i * 32]);
        #pragma unroll
        for (int o = 16; o > 0; o >>= 1)
            mx = fmaxf(mx, __shfl_xor_sync(0xffffffffu, mx, o));
        float sum = 0.f;
        #pragma unroll
        for (int i = 0; i < 32; i++) {
            float p = __expf(row[lane + i * 32] - mx);
            row[lane + i * 32] = p;
            sum += p;
        }
        #pragma unroll
        for (int o = 16; o > 0; o >>= 1)
            sum += __shfl_xor_sync(0xffffffffu, sum, o);
        float inv = 1.f / sum;
        #pragma unroll
        for (int i = 0; i < 32; i++) row[lane + i * 32] *= inv;
    }

    float a00 = 0.f, a01 = 0.f, a10 = 0.f, a11 = 0.f;
    const int q0 = w * 2, d0 = lane, d1 = lane + 32;

    for (int c = 0; c < 4; c++) {
        __syncthreads();
        {
            const int t = c * 256 + tid;
            const float* vp = g_v + ((size_t)(b * Sn + t)) * Dn + h * DKn;
            #pragma unroll
            for (int i = 0; i < 16; i++) {
                float4 v = *(const float4*)(vp + i * 4);
                sVT[(i * 4 + 0) * VSTR + tid] = v.x;
                sVT[(i * 4 + 1) * VSTR + tid] = v.y;
                sVT[(i * 4 + 2) * VSTR + tid] = v.z;
                sVT[(i * 4 + 3) * VSTR + tid] = v.w;
            }
        }
        __syncthreads();

        const float* P0 = &sS[q0 * Sn + c * 256];
        const float* P1 = &sS[(q0 + 1) * Sn + c * 256];
        const float* V0 = &sVT[(size_t)d0 * VSTR];
        const float* V1 = &sVT[(size_t)d1 * VSTR];
        #pragma unroll 8
        for (int kk = 0; kk < 256; kk += 4) {
            float4 p0 = *(const float4*)(P0 + kk);
            float4 p1 = *(const float4*)(P1 + kk);
            float4 v0 = *(const float4*)(V0 + kk);
            float4 v1 = *(const float4*)(V1 + kk);
            a00 += p0.x * v0.x + p0.y * v0.y + p0.z * v0.z + p0.w * v0.w;
            a01 += p0.x * v1.x + p0.y * v1.y + p0.z * v1.z + p0.w * v1.w;
            a10 += p1.x * v0.x + p1.y * v0.y + p1.z * v0.z + p1.w * v0.w;
            a11 += p1.x * v1.x + p1.y * v1.y + p1.z * v1.z + p1.w * v1.w;
        }
    }

    float* cp = g_ctx + ((size_t)(b * Sn + s0 + q0)) * Dn + h * DKn;
    cp[d0]      = a00;
    cp[d1]      = a01;
    cp[Dn + d0] = a10;
    cp[Dn + d1] = a11;
}

// ======================== LayerNorm ==========================================
__global__ __launch_bounds__(256) void ln_partial_k()
{
    const int blk = blockIdx.x;
    const int b   = blk / 32;
    const int seg = blk % 32;
    const float* base = g_res + (size_t)b * Sn * Dn + (size_t)seg * 32768;

    float s = 0.f, s2 = 0.f;
    for (int i = threadIdx.x; i < 32768; i += 256) {
        float v = base[i];
        s += v;
        s2 += v * v;
    }
    __shared__ double sh1[256], sh2[256];
    sh1[threadIdx.x] = (double)s;
    sh2[threadIdx.x] = (double)s2;
    __syncthreads();
    for (int o = 128; o > 0; o >>= 1) {
        if (threadIdx.x < o) {
            sh1[threadIdx.x] += sh1[threadIdx.x + o];
            sh2[threadIdx.x] += sh2[threadIdx.x + o];
        }
        __syncthreads();
    }
    if (threadIdx.x == 0) {
        g_part[blk * 2 + 0] = sh1[0];
        g_part[blk * 2 + 1] = sh2[0];
    }
}

__global__ void ln_finish_k()
{
    const int b = blockIdx.x;
    const int l = threadIdx.x;
    __shared__ double sh[64];
    sh[l]      = g_part[(b * 32 + l) * 2 + 0];
    sh[32 + l] = g_part[(b * 32 + l) * 2 + 1];
    __syncthreads();
    if (l == 0) {
        double S = 0.0, S2 = 0.0;
        for (int i = 0; i < 32; i++) { S += sh[i]; S2 += sh[32 + i]; }
        const double N = (double)Sn * (double)Dn;
        double mean = S / N;
        double var  = S2 / N - mean * mean;
        g_stats[b * 2 + 0] = (float)mean;
        g_stats[b * 2 + 1] = (float)(1.0 / sqrt(var + 1e-5));
    }
}

__global__ __launch_bounds__(256) void ln_norm_k(float* __restrict__ out)
{
    const int idx = blockIdx.x * 256 + threadIdx.x;
    const size_t i4 = (size_t)idx * 4;
    const int b = (int)(i4 >> 20);
    const float mean = g_stats[b * 2 + 0];
    const float istd = g_stats[b * 2 + 1];
    float4 v = *(const float4*)&g_res[i4];
    v.x = (v.x - mean) * istd;
    v.y = (v.y - mean) * istd;
    v.z = (v.z - mean) * istd;
    v.w = (v.w - mean) * istd;
    *(float4*)&out[i4] = v;
}

// =============================================================================
extern "C" void kernel_launch(void* const* d_in, const int* in_sizes, int n_in,
                              void* d_out, int out_size)
{
    const int*   mask = (const int*)  d_in[0];
    const float* x    = (const float*)d_in[1];
    const float* wq   = (const float*)d_in[2];
    const float* wk   = (const float*)d_in[3];
    const float* wv   = (const float*)d_in[4];
    const float* wo   = (const float*)d_in[5];
    float* out = (float*)d_out;

    const int smem_attn = (QT * 64 + QT * Sn + 64 * VSTR) * (int)sizeof(float);
    cudaFuncSetAttribute(attn_k, cudaFuncAttributeMaxDynamicSharedMemorySize, smem_attn);

    // 0) bf16 split conversions
    cvt_split_k<<<(Bn * Sn * Dn) / (256 * 4), 256>>>(x, 0);
    cvt_wqkv_k<<<(3 * Dn * Dn) / 256, 256>>>(wq, wk, wv);
    cvt_wo_k<<<dim3(Dn / 32, Dn / 32), dim3(32, 8)>>>(wo);

    // 1) fused QKV projection (HMMA split-bf16)
    gemm_mma_k<<<dim3(24, 64), 256>>>(nullptr, 0);

    // 2) attention
    attn_k<<<Bn * Hn * (Sn / QT), 256, smem_attn>>>(mask);

    // 3) output projection + residual (HMMA split-bf16)
    cvt_split_k<<<(Bn * Sn * Dn) / (256 * 4), 256>>>(nullptr, 1);
    gemm_mma_k<<<dim3(8, 64), 256>>>(x, 1);

    // 4) layernorm over (S, D) per batch
    ln_partial_k<<<Bn * 32, 256>>>();
    ln_finish_k<<<Bn, 32>>>();
    ln_norm_k<<<(Bn * Sn * Dn) / (256 * 4), 256>>>(out);
}

// round 14
// speedup vs baseline: 1.0006x; 1.0006x over previous
#include <cuda_runtime.h>
#include <cuda_bf16.h>
#include <math.h>
#include <stdint.h>

#define Bn  8
#define Sn  1024
#define Dn  1024
#define Hn  16
#define DKn 64
#define QT  16
#define VSTR 260

// ---------------- scratch (device globals; no allocation allowed) -------------
__device__ __align__(256) float g_q  [Bn*Sn*Dn];
__device__ __align__(256) float g_k  [Bn*Sn*Dn];
__device__ __align__(256) float g_v  [Bn*Sn*Dn];
__device__ __align__(256) float g_ctx[Bn*Sn*Dn];
__device__ __align__(256) float g_res[Bn*Sn*Dn];
__device__ double g_part[Bn*32*2];
__device__ float g_stats[Bn*2];

// bf16 split scratch
__device__ __align__(256) __nv_bfloat16 g_xhi[Bn*Sn*Dn];
__device__ __align__(256) __nv_bfloat16 g_xlo[Bn*Sn*Dn];
__device__ __align__(256) __nv_bfloat16 g_chi[Bn*Sn*Dn];
__device__ __align__(256) __nv_bfloat16 g_clo[Bn*Sn*Dn];
__device__ __align__(256) __nv_bfloat16 g_bthi[3*Dn*Dn];   // qkv weights, Bt[n][k]
__device__ __align__(256) __nv_bfloat16 g_btlo[3*Dn*Dn];
__device__ __align__(256) __nv_bfloat16 g_wohi[Dn*Dn];     // wo^T, Bt[n][k]=WO[k][n]
__device__ __align__(256) __nv_bfloat16 g_wolo[Dn*Dn];

// ---------------- mma.sync helper (sm_80+ path, compiles on compute_103) ------
__device__ __forceinline__ void mma16816(float* c, const uint32_t* a, const uint32_t* b)
{
    asm volatile(
        "mma.sync.aligned.m16n8k16.row.col.f32.bf16.bf16.f32 "
        "{%0,%1,%2,%3}, {%4,%5,%6,%7}, {%8,%9}, {%0,%1,%2,%3};"
        : "+f"(c[0]), "+f"(c[1]), "+f"(c[2]), "+f"(c[3])
        : "r"(a[0]), "r"(a[1]), "r"(a[2]), "r"(a[3]), "r"(b[0]), "r"(b[1]));
}

// ======================== conversion kernels =================================
__global__ __launch_bounds__(256) void cvt_split_k(const float* __restrict__ xext, int which)
{
    const float* src = which ? g_ctx : xext;
    __nv_bfloat16* hi = which ? g_chi : g_xhi;
    __nv_bfloat16* lo = which ? g_clo : g_xlo;
    size_t i = ((size_t)blockIdx.x * 256 + threadIdx.x) * 4;
    float4 v = *(const float4*)(src + i);
    __nv_bfloat16 h0 = __float2bfloat16(v.x), l0 = __float2bfloat16(v.x - __bfloat162float(h0));
    __nv_bfloat16 h1 = __float2bfloat16(v.y), l1 = __float2bfloat16(v.y - __bfloat162float(h1));
    __nv_bfloat16 h2 = __float2bfloat16(v.z), l2 = __float2bfloat16(v.z - __bfloat162float(h2));
    __nv_bfloat16 h3 = __float2bfloat16(v.w), l3 = __float2bfloat16(v.w - __bfloat162float(h3));
    *(__nv_bfloat162*)(hi + i)     = __halves2bfloat162(h0, h1);
    *(__nv_bfloat162*)(hi + i + 2) = __halves2bfloat162(h2, h3);
    *(__nv_bfloat162*)(lo + i)     = __halves2bfloat162(l0, l1);
    *(__nv_bfloat162*)(lo + i + 2) = __halves2bfloat162(l2, l3);
}

// Bt_qkv[n][k] = Wsel[h][k][kk], n in [0,3072), h=(n%1024)/64, kk=n%64
__global__ __launch_bounds__(256) void cvt_wqkv_k(const float* __restrict__ WQ,
                                                  const float* __restrict__ WK,
                                                  const float* __restrict__ WV)
{
    size_t idx = (size_t)blockIdx.x * 256 + threadIdx.x;   // over 3072*1024
    int k = (int)(idx & 1023);
    int n = (int)(idx >> 10);
    int within = n & 1023, sel = n >> 10;
    const float* W = (sel == 0) ? WQ : (sel == 1 ? WK : WV);
    float w = W[(size_t)(within >> 6) * (Dn * DKn) + (size_t)k * DKn + (within & 63)];
    __nv_bfloat16 h = __float2bfloat16(w);
    g_bthi[idx] = h;
    g_btlo[idx] = __float2bfloat16(w - __bfloat162float(h));
}

// Bt_wo[n][k] = WO[k][n]  (tiled transpose + split)
__global__ __launch_bounds__(256) void cvt_wo_k(const float* __restrict__ WO)
{
    __shared__ float t[32][33];
    const int x = threadIdx.x, y = threadIdx.y;       // (32, 8)
    const int bx = blockIdx.x, by = blockIdx.y;
    #pragma unroll
    for (int i = 0; i < 4; i++)
        t[y + i * 8][x] = WO[(size_t)(by * 32 + y + i * 8) * Dn + bx * 32 + x];
    __syncthreads();
    #pragma unroll
    for (int i = 0; i < 4; i++) {
        float w = t[x][y + i * 8];
        __nv_bfloat16 h = __float2bfloat16(w);
        size_t o = (size_t)(bx * 32 + y + i * 8) * Dn + by * 32 + x;
        g_wohi[o] = h;
        g_wolo[o] = __float2bfloat16(w - __bfloat162float(h));
    }
}

// ======================== split-bf16 HMMA GEMM ===============================
// C[M x N] = A * Bt^T (Bt is [N][K] K-major). 128x128 tile, 8 warps (2x4),
// warp tile 64x32 (4x4 m16n8k16 frags), K-step 16, double-buffered SMEM.
// 3-pass split accumulate: Ahi*Bhi + Ahi*Blo + Alo*Bhi (fp32 accum).
// mode 0: qkv (OUT among g_q/g_k/g_v by n block); mode 1: out proj + residual.
__global__ __launch_bounds__(256, 1) void gemm_mma_k(const float* __restrict__ Xres, int mode)
{
    __shared__ __align__(16) __nv_bfloat16 sA[2][2][128 * 16];
    __shared__ __align__(16) __nv_bfloat16 sB[2][2][128 * 16];

    const int tid  = threadIdx.x;
    const int wid  = tid >> 5, lane = tid & 31;
    const int g    = lane >> 2, tg = lane & 3;
    const int m0   = blockIdx.y * 128;
    const int n0g  = blockIdx.x * 128;
    const int mo   = (wid >> 2) * 64;     // warp row offset in tile
    const int no   = (wid & 3) * 32;      // warp col offset in tile

    const __nv_bfloat16* Ahi = mode ? g_chi : g_xhi;
    const __nv_bfloat16* Alo = mode ? g_clo : g_xlo;
    const __nv_bfloat16* Bhi = mode ? g_wohi : g_bthi;
    const __nv_bfloat16* Blo = mode ? g_wolo : g_btlo;

    // loaders: thread covers one 8-bf16 segment; row = tid/2, seg = (tid&1)*8
    const int lrow = tid >> 1;
    const int lseg = (tid & 1) * 8;
    const __nv_bfloat16* pAhi = Ahi + (size_t)(m0 + lrow) * Dn + lseg;
    const __nv_bfloat16* pAlo = Alo + (size_t)(m0 + lrow) * Dn + lseg;
    const __nv_bfloat16* pBhi = Bhi + (size_t)(n0g + lrow) * Dn + lseg;
    const __nv_bfloat16* pBlo = Blo + (size_t)(n0g + lrow) * Dn + lseg;
    const int soff = lrow * 16 + lseg;

    float c[4][4][4];
    #pragma unroll
    for (int i = 0; i < 4; i++)
        #pragma unroll
        for (int j = 0; j < 4; j++)
            #pragma unroll
            for (int r = 0; r < 4; r++) c[i][j][r] = 0.f;

    // prologue: stage 0
    *(uint4*)&sA[0][0][soff] = *(const uint4*)pAhi;
    *(uint4*)&sA[0][1][soff] = *(const uint4*)pAlo;
    *(uint4*)&sB[0][0][soff] = *(const uint4*)pBhi;
    *(uint4*)&sB[0][1][soff] = *(const uint4*)pBlo;
    __syncthreads();

    const int NK = Dn / 16;   // 64
    for (int ks = 0; ks < NK; ks++) {
        const int cur = ks & 1;

        uint4 va, vb, vc, vd;
        if (ks < NK - 1) {
            const int k0 = (ks + 1) * 16;
            va = *(const uint4*)(pAhi + k0);
            vb = *(const uint4*)(pAlo + k0);
            vc = *(const uint4*)(pBhi + k0);
            vd = *(const uint4*)(pBlo + k0);
        }

        // load fragments
        uint32_t a[2][4][4];
        #pragma unroll
        for (int sp = 0; sp < 2; sp++) {
            const __nv_bfloat16* base = &sA[cur][sp][0];
            #pragma unroll
            for (int i = 0; i < 4; i++) {
                int r = (mo + i * 16 + g) * 16 + tg * 2;
                a[sp][i][0] = *(const uint32_t*)&base[r];
                a[sp][i][1] = *(const uint32_t*)&base[r + 8 * 16];
                a[sp][i][2] = *(const uint32_t*)&base[r + 8];
                a[sp][i][3] = *(const uint32_t*)&base[r + 8 * 16 + 8];
            }
        }
        uint32_t b[2][4][2];
        #pragma unroll
        for (int sp = 0; sp < 2; sp++) {
            const __nv_bfloat16* base = &sB[cur][sp][0];
            #pragma unroll
            for (int j = 0; j < 4; j++) {
                int r = (no + j * 8 + g) * 16 + tg * 2;
                b[sp][j][0] = *(const uint32_t*)&base[r];
                b[sp][j][1] = *(const uint32_t*)&base[r + 8];
            }
        }

        // 3-pass MMAs
        #pragma unroll
        for (int i = 0; i < 4; i++)
            #pragma unroll
            for (int j = 0; j < 4; j++) {
                mma16816(c[i][j], a[0][i], b[0][j]);   // hi*hi
                mma16816(c[i][j], a[0][i], b[1][j]);   // hi*lo
                mma16816(c[i][j], a[1][i], b[0][j]);   // lo*hi
            }

        if (ks < NK - 1) {
            const int nb = cur ^ 1;
            *(uint4*)&sA[nb][0][soff] = va;
            *(uint4*)&sA[nb][1][soff] = vb;
            *(uint4*)&sB[nb][0][soff] = vc;
            *(uint4*)&sB[nb][1][soff] = vd;
            __syncthreads();
        }
    }

    // epilogue
    float* OUT;
    int nbase;
    if (mode == 0) {
        int sel = n0g >> 10;
        OUT = (sel == 0) ? g_q : (sel == 1 ? g_k : g_v);
        nbase = n0g & 1023;
    } else {
        OUT = g_res;
        nbase = n0g;
    }

    #pragma unroll
    for (int i = 0; i < 4; i++) {
        #pragma unroll
        for (int j = 0; j < 4; j++) {
            const int r0  = m0 + mo + i * 16 + g;
            const int col = nbase + no + j * 8 + tg * 2;
            size_t o0 = (size_t)r0 * Dn + col;
            size_t o1 = (size_t)(r0 + 8) * Dn + col;
            float2 v0 = make_float2(c[i][j][0], c[i][j][1]);
            float2 v1 = make_float2(c[i][j][2], c[i][j][3]);
            if (mode == 1) {
                float2 x0 = *(const float2*)(Xres + o0);
                float2 x1 = *(const float2*)(Xres + o1);
                v0.x += x0.x; v0.y += x0.y;
                v1.x += x1.x; v1.y += x1.y;
            }
            *(float2*)(OUT + o0) = v0;
            *(float2*)(OUT + o1) = v1;
        }
    }
}

// ======================== attention (unchanged) ==============================
__global__ __launch_bounds__(256) void attn_k(const int* __restrict__ mask)
{
    extern __shared__ float sh[];
    float* sQ  = sh;
    float* sS  = sh + QT * 64;
    float* sVT = sS + QT * Sn;

    const int tid  = threadIdx.x;
    const int blk  = blockIdx.x;
    const int tile = blk % (Sn / QT);
    const int h    = (blk / (Sn / QT)) % Hn;
    const int b    = blk / ((Sn / QT) * Hn);
    const int s0   = tile * QT;

    {
        int j  = tid / 16;
        int d4 = (tid % 16) * 4;
        const float* qp = g_q + ((size_t)(b * Sn + s0 + j)) * Dn + h * DKn + d4;
        *(float4*)&sQ[j * 64 + d4] = *(const float4*)qp;
    }
    __syncthreads();

    const float scale = 0.125f;
    for (int c = 0; c < 4; c++) {
        const int t = c * 256 + tid;
        const float* kp = g_k + ((size_t)(b * Sn + t)) * Dn + h * DKn;
        float kreg[64];
        #pragma unroll
        for (int i = 0; i < 16; i++)
            *(float4*)&kreg[i * 4] = *(const float4*)(kp + i * 4);

        #pragma unroll
        for (int j = 0; j < QT; j++) {
            float s = 0.f;
            #pragma unroll
            for (int i = 0; i < 16; i++) {
                float4 qv = *(const float4*)&sQ[j * 64 + i * 4];
                s += qv.x * kreg[i * 4 + 0];
                s += qv.y * kreg[i * 4 + 1];
                s += qv.z * kreg[i * 4 + 2];
                s += qv.w * kreg[i * 4 + 3];
            }
            int m = mask[((size_t)(b * Sn) + (s0 + j)) * Sn + t];
            sS[j * Sn + t] = (m != 0) ? s * scale : -1e9f;
        }
    }
    __syncthreads();

    const int w = tid / 32, lane = tid % 32;
    #pragma unroll
    for (int rr = 0; rr < 2; rr++) {
        float* row = &sS[(w * 2 + rr) * Sn];
        float mx = -1e30f;
        #pragma unroll
        for (int i = 0; i < 32; i++) mx = fmaxf(mx, row[lane + i * 32]);
        #pragma unroll
        for (int o = 16; o > 0; o >>= 1)
            mx = fmaxf(mx, __shfl_xor_sync(0xffffffffu, mx, o));
        float sum = 0.f;
        #pragma unroll
        for (int i = 0; i < 32; i++) {
            float p = __expf(row[lane + i * 32] - mx);
            row[lane + i * 32] = p;
            sum += p;
        }
        #pragma unroll
        for (int o = 16; o > 0; o >>= 1)
            sum += __shfl_xor_sync(0xffffffffu, sum, o);
        float inv = 1.f / sum;
        #pragma unroll
        for (int i = 0; i < 32; i++) row[lane + i * 32] *= inv;
    }

    float a00 = 0.f, a01 = 0.f, a10 = 0.f, a11 = 0.f;
    const int q0 = w * 2, d0 = lane, d1 = lane + 32;

    for (int c = 0; c < 4; c++) {
        __syncthreads();
        {
            const int t = c * 256 + tid;
            const float* vp = g_v + ((size_t)(b * Sn + t)) * Dn + h * DKn;
            #pragma unroll
            for (int i = 0; i < 16; i++) {
                float4 v = *(const float4*)(vp + i * 4);
                sVT[(i * 4 + 0) * VSTR + tid] = v.x;
                sVT[(i * 4 + 1) * VSTR + tid] = v.y;
                sVT[(i * 4 + 2) * VSTR + tid] = v.z;
                sVT[(i * 4 + 3) * VSTR + tid] = v.w;
            }
        }
        __syncthreads();

        const float* P0 = &sS[q0 * Sn + c * 256];
        const float* P1 = &sS[(q0 + 1) * Sn + c * 256];
        const float* V0 = &sVT[(size_t)d0 * VSTR];
        const float* V1 = &sVT[(size_t)d1 * VSTR];
        #pragma unroll 8
        for (int kk = 0; kk < 256; kk += 4) {
            float4 p0 = *(const float4*)(P0 + kk);
            float4 p1 = *(const float4*)(P1 + kk);
            float4 v0 = *(const float4*)(V0 + kk);
            float4 v1 = *(const float4*)(V1 + kk);
            a00 += p0.x * v0.x + p0.y * v0.y + p0.z * v0.z + p0.w * v0.w;
            a01 += p0.x * v1.x + p0.y * v1.y + p0.z * v1.z + p0.w * v1.w;
            a10 += p1.x * v0.x + p1.y * v0.y + p1.z * v0.z + p1.w * v0.w;
            a11 += p1.x * v1.x + p1.y * v1.y + p1.z * v1.z + p1.w * v1.w;
        }
    }

    float* cp = g_ctx + ((size_t)(b * Sn + s0 + q0)) * Dn + h * DKn;
    cp[d0]      = a00;
    cp[d1]      = a01;
    cp[Dn + d0] = a10;
    cp[Dn + d1] = a11;
}

// ======================== LayerNorm ==========================================
__global__ __launch_bounds__(256) void ln_partial_k()
{
    const int blk = blockIdx.x;
    const int b   = blk / 32;
    const int seg = blk % 32;
    const float* base = g_res + (size_t)b * Sn * Dn + (size_t)seg * 32768;

    float s = 0.f, s2 = 0.f;
    for (int i = threadIdx.x; i < 32768; i += 256) {
        float v = base[i];
        s += v;
        s2 += v * v;
    }
    __shared__ double sh1[256], sh2[256];
    sh1[threadIdx.x] = (double)s;
    sh2[threadIdx.x] = (double)s2;
    __syncthreads();
    for (int o = 128; o > 0; o >>= 1) {
        if (threadIdx.x < o) {
            sh1[threadIdx.x] += sh1[threadIdx.x + o];
            sh2[threadIdx.x] += sh2[threadIdx.x + o];
        }
        __syncthreads();
    }
    if (threadIdx.x == 0) {
        g_part[blk * 2 + 0] = sh1[0];
        g_part[blk * 2 + 1] = sh2[0];
    }
}

__global__ void ln_finish_k()
{
    const int b = blockIdx.x;
    const int l = threadIdx.x;
    __shared__ double sh[64];
    sh[l]      = g_part[(b * 32 + l) * 2 + 0];
    sh[32 + l] = g_part[(b * 32 + l) * 2 + 1];
    __syncthreads();
    if (l == 0) {
        double S = 0.0, S2 = 0.0;
        for (int i = 0; i < 32; i++) { S += sh[i]; S2 += sh[32 + i]; }
        const double N = (double)Sn * (double)Dn;
        double mean = S / N;
        double var  = S2 / N - mean * mean;
        g_stats[b * 2 + 0] = (float)mean;
        g_stats[b * 2 + 1] = (float)(1.0 / sqrt(var + 1e-5));
    }
}

__global__ __launch_bounds__(256) void ln_norm_k(float* __restrict__ out)
{
    const int idx = blockIdx.x * 256 + threadIdx.x;
    const size_t i4 = (size_t)idx * 4;
    const int b = (int)(i4 >> 20);
    const float mean = g_stats[b * 2 + 0];
    const float istd = g_stats[b * 2 + 1];
    float4 v = *(const float4*)&g_res[i4];
    v.x = (v.x - mean) * istd;
    v.y = (v.y - mean) * istd;
    v.z = (v.z - mean) * istd;
    v.w = (v.w - mean) * istd;
    *(float4*)&out[i4] = v;
}

// =============================================================================
extern "C" void kernel_launch(void* const* d_in, const int* in_sizes, int n_in,
                              void* d_out, int out_size)
{
    const int*   mask = (const int*)  d_in[0];
    const float* x    = (const float*)d_in[1];
    const float* wq   = (const float*)d_in[2];
    const float* wk   = (const float*)d_in[3];
    const float* wv   = (const float*)d_in[4];
    const float* wo   = (const float*)d_in[5];
    float* out = (float*)d_out;

    const int smem_attn = (QT * 64 + QT * Sn + 64 * VSTR) * (int)sizeof(float);
    cudaFuncSetAttribute(attn_k, cudaFuncAttributeMaxDynamicSharedMemorySize, smem_attn);

    // 0) bf16 split conversions
    cvt_split_k<<<(Bn * Sn * Dn) / (256 * 4), 256>>>(x, 0);
    cvt_wqkv_k<<<(3 * Dn * Dn) / 256, 256>>>(wq, wk, wv);
    cvt_wo_k<<<dim3(Dn / 32, Dn / 32), dim3(32, 8)>>>(wo);

    // 1) fused QKV projection (HMMA split-bf16)
    gemm_mma_k<<<dim3(24, 64), 256>>>(nullptr, 0);

    // 2) attention
    attn_k<<<Bn * Hn * (Sn / QT), 256, smem_attn>>>(mask);

    // 3) output projection + residual (HMMA split-bf16)
    cvt_split_k<<<(Bn * Sn * Dn) / (256 * 4), 256>>>(nullptr, 1);
    gemm_mma_k<<<dim3(8, 64), 256>>>(x, 1);

    // 4) layernorm over (S, D) per batch
    ln_partial_k<<<Bn * 32, 256>>>();
    ln_finish_k<<<Bn, 32>>>();
    ln_norm_k<<<(Bn * Sn * Dn) / (256 * 4), 256>>>(out);
}

// round 15
// speedup vs baseline: 10.9751x; 10.9682x over previous
#include <cuda_runtime.h>
#include <cuda_bf16.h>
#include <math.h>
#include <stdint.h>

#define Bn  8
#define Sn  1024
#define Dn  1024
#define Hn  16
#define DKn 64

// ---------------- scratch (device globals; no allocation allowed) -------------
__device__ __align__(256) float g_res[Bn*Sn*Dn];
__device__ double g_part[Bn*32*2];
__device__ float g_stats[Bn*2];

// bf16 split scratch
__device__ __align__(256) __nv_bfloat16 g_xhi[Bn*Sn*Dn];
__device__ __align__(256) __nv_bfloat16 g_xlo[Bn*Sn*Dn];
__device__ __align__(256) __nv_bfloat16 g_chi[Bn*Sn*Dn];   // ctx hi (attn out)
__device__ __align__(256) __nv_bfloat16 g_clo[Bn*Sn*Dn];
__device__ __align__(256) __nv_bfloat16 g_bthi[3*Dn*Dn];   // qkv weights, Bt[n][k]
__device__ __align__(256) __nv_bfloat16 g_btlo[3*Dn*Dn];
__device__ __align__(256) __nv_bfloat16 g_wohi[Dn*Dn];     // wo^T
__device__ __align__(256) __nv_bfloat16 g_wolo[Dn*Dn];

// q/k split [b*S+s][h*64+d]; v split transposed [(b*H+h)*64+d][t]
__device__ __align__(256) __nv_bfloat16 g_qhi[Bn*Sn*Dn];
__device__ __align__(256) __nv_bfloat16 g_qlo[Bn*Sn*Dn];
__device__ __align__(256) __nv_bfloat16 g_khi[Bn*Sn*Dn];
__device__ __align__(256) __nv_bfloat16 g_klo[Bn*Sn*Dn];
__device__ __align__(256) __nv_bfloat16 g_vthi[Bn*Hn*DKn*Sn];
__device__ __align__(256) __nv_bfloat16 g_vtlo[Bn*Hn*DKn*Sn];

// ---------------- helpers ----------------------------------------------------
__device__ __forceinline__ void mma16816(float* c, const uint32_t* a, const uint32_t* b)
{
    asm volatile(
        "mma.sync.aligned.m16n8k16.row.col.f32.bf16.bf16.f32 "
        "{%0,%1,%2,%3}, {%4,%5,%6,%7}, {%8,%9}, {%0,%1,%2,%3};"
        : "+f"(c[0]), "+f"(c[1]), "+f"(c[2]), "+f"(c[3])
        : "r"(a[0]), "r"(a[1]), "r"(a[2]), "r"(a[3]), "r"(b[0]), "r"(b[1]));
}
__device__ __forceinline__ uint32_t smem_u32(const void* p) {
    uint32_t a;
    asm("{ .reg .u64 t; cvta.to.shared.u64 t, %1; cvt.u32.u64 %0, t; }"
        : "=r"(a) : "l"(p));
    return a;
}
__device__ __forceinline__ uint32_t lds32(uint32_t a) {
    uint32_t v;
    asm volatile("ld.shared.b32 %0, [%1];" : "=r"(v) : "r"(a));
    return v;
}
__device__ __forceinline__ uint32_t pack_bf16(__nv_bfloat16 a, __nv_bfloat16 b) {
    __nv_bfloat162 t = __halves2bfloat162(a, b);
    return *(uint32_t*)&t;
}
#define CP16(sm, gp) \
    asm volatile("cp.async.cg.shared.global [%0], [%1], 16;" :: "r"(sm), "l"(gp) : "memory")
#define CP_COMMIT() asm volatile("cp.async.commit_group;" ::: "memory")
#define CP_WAIT(n)  asm volatile("cp.async.wait_group %0;" :: "n"(n) : "memory")

// ======================== conversion kernels =================================
__global__ __launch_bounds__(256) void cvt_split_k(const float* __restrict__ src)
{
    size_t i = ((size_t)blockIdx.x * 256 + threadIdx.x) * 4;
    float4 v = *(const float4*)(src + i);
    __nv_bfloat16 h0 = __float2bfloat16(v.x), l0 = __float2bfloat16(v.x - __bfloat162float(h0));
    __nv_bfloat16 h1 = __float2bfloat16(v.y), l1 = __float2bfloat16(v.y - __bfloat162float(h1));
    __nv_bfloat16 h2 = __float2bfloat16(v.z), l2 = __float2bfloat16(v.z - __bfloat162float(h2));
    __nv_bfloat16 h3 = __float2bfloat16(v.w), l3 = __float2bfloat16(v.w - __bfloat162float(h3));
    *(__nv_bfloat162*)(g_xhi + i)     = __halves2bfloat162(h0, h1);
    *(__nv_bfloat162*)(g_xhi + i + 2) = __halves2bfloat162(h2, h3);
    *(__nv_bfloat162*)(g_xlo + i)     = __halves2bfloat162(l0, l1);
    *(__nv_bfloat162*)(g_xlo + i + 2) = __halves2bfloat162(l2, l3);
}

__global__ __launch_bounds__(256) void cvt_wqkv_k(const float* __restrict__ WQ,
                                                  const float* __restrict__ WK,
                                                  const float* __restrict__ WV)
{
    size_t idx = (size_t)blockIdx.x * 256 + threadIdx.x;
    int k = (int)(idx & 1023);
    int n = (int)(idx >> 10);
    int within = n & 1023, sel = n >> 10;
    const float* W = (sel == 0) ? WQ : (sel == 1 ? WK : WV);
    float w = W[(size_t)(within >> 6) * (Dn * DKn) + (size_t)k * DKn + (within & 63)];
    __nv_bfloat16 h = __float2bfloat16(w);
    g_bthi[idx] = h;
    g_btlo[idx] = __float2bfloat16(w - __bfloat162float(h));
}

__global__ __launch_bounds__(256) void cvt_wo_k(const float* __restrict__ WO)
{
    __shared__ float t[32][33];
    const int x = threadIdx.x, y = threadIdx.y;
    const int bx = blockIdx.x, by = blockIdx.y;
    #pragma unroll
    for (int i = 0; i < 4; i++)
        t[y + i * 8][x] = WO[(size_t)(by * 32 + y + i * 8) * Dn + bx * 32 + x];
    __syncthreads();
    #pragma unroll
    for (int i = 0; i < 4; i++) {
        float w = t[x][y + i * 8];
        __nv_bfloat16 h = __float2bfloat16(w);
        size_t o = (size_t)(bx * 32 + y + i * 8) * Dn + by * 32 + x;
        g_wohi[o] = h;
        g_wolo[o] = __float2bfloat16(w - __bfloat162float(h));
    }
}

// ======================== split-bf16 HMMA GEMM ===============================
// mode 0: qkv. A = x splits, B = qkv weights. Writes q/k bf16 splits and
//         V TRANSPOSED bf16 splits (for flash attention B-fragments).
// mode 1: out proj. A = ctx splits, B = wo^T splits. Writes g_res fp32 + residual.
__global__ __launch_bounds__(256, 1) void gemm_mma_k(const float* __restrict__ Xres, int mode)
{
    __shared__ __align__(16) __nv_bfloat16 sA[2][2][128 * 16];
    __shared__ __align__(16) __nv_bfloat16 sB[2][2][128 * 16];

    const int tid  = threadIdx.x;
    const int wid  = tid >> 5, lane = tid & 31;
    const int g    = lane >> 2, tg = lane & 3;
    const int m0   = blockIdx.y * 128;
    const int n0g  = blockIdx.x * 128;
    const int mo   = (wid >> 2) * 64;
    const int no   = (wid & 3) * 32;

    const __nv_bfloat16* Ahi = mode ? g_chi : g_xhi;
    const __nv_bfloat16* Alo = mode ? g_clo : g_xlo;
    const __nv_bfloat16* Bhi = mode ? g_wohi : g_bthi;
    const __nv_bfloat16* Blo = mode ? g_wolo : g_btlo;

    const int lrow = tid >> 1;
    const int lseg = (tid & 1) * 8;
    const __nv_bfloat16* pAhi = Ahi + (size_t)(m0 + lrow) * Dn + lseg;
    const __nv_bfloat16* pAlo = Alo + (size_t)(m0 + lrow) * Dn + lseg;
    const __nv_bfloat16* pBhi = Bhi + (size_t)(n0g + lrow) * Dn + lseg;
    const __nv_bfloat16* pBlo = Blo + (size_t)(n0g + lrow) * Dn + lseg;
    const int soff = lrow * 16 + lseg;

    float c[4][4][4];
    #pragma unroll
    for (int i = 0; i < 4; i++)
        #pragma unroll
        for (int j = 0; j < 4; j++)
            #pragma unroll
            for (int r = 0; r < 4; r++) c[i][j][r] = 0.f;

    *(uint4*)&sA[0][0][soff] = *(const uint4*)pAhi;
    *(uint4*)&sA[0][1][soff] = *(const uint4*)pAlo;
    *(uint4*)&sB[0][0][soff] = *(const uint4*)pBhi;
    *(uint4*)&sB[0][1][soff] = *(const uint4*)pBlo;
    __syncthreads();

    const int NK = Dn / 16;
    for (int ks = 0; ks < NK; ks++) {
        const int cur = ks & 1;
        uint4 va, vb, vc, vd;
        if (ks < NK - 1) {
            const int k0 = (ks + 1) * 16;
            va = *(const uint4*)(pAhi + k0);
            vb = *(const uint4*)(pAlo + k0);
            vc = *(const uint4*)(pBhi + k0);
            vd = *(const uint4*)(pBlo + k0);
        }

        uint32_t a[2][4][4];
        #pragma unroll
        for (int sp = 0; sp < 2; sp++) {
            const __nv_bfloat16* base = &sA[cur][sp][0];
            #pragma unroll
            for (int i = 0; i < 4; i++) {
                int r = (mo + i * 16 + g) * 16 + tg * 2;
                a[sp][i][0] = *(const uint32_t*)&base[r];
                a[sp][i][1] = *(const uint32_t*)&base[r + 8 * 16];
                a[sp][i][2] = *(const uint32_t*)&base[r + 8];
                a[sp][i][3] = *(const uint32_t*)&base[r + 8 * 16 + 8];
            }
        }
        uint32_t b[2][4][2];
        #pragma unroll
        for (int sp = 0; sp < 2; sp++) {
            const __nv_bfloat16* base = &sB[cur][sp][0];
            #pragma unroll
            for (int j = 0; j < 4; j++) {
                int r = (no + j * 8 + g) * 16 + tg * 2;
                b[sp][j][0] = *(const uint32_t*)&base[r];
                b[sp][j][1] = *(const uint32_t*)&base[r + 8];
            }
        }

        #pragma unroll
        for (int i = 0; i < 4; i++)
            #pragma unroll
            for (int j = 0; j < 4; j++) {
                mma16816(c[i][j], a[0][i], b[0][j]);
                mma16816(c[i][j], a[0][i], b[1][j]);
                mma16816(c[i][j], a[1][i], b[0][j]);
            }

        if (ks < NK - 1) {
            const int nb = cur ^ 1;
            *(uint4*)&sA[nb][0][soff] = va;
            *(uint4*)&sA[nb][1][soff] = vb;
            *(uint4*)&sB[nb][0][soff] = vc;
            *(uint4*)&sB[nb][1][soff] = vd;
            __syncthreads();
        }
    }

    if (mode == 1) {
        #pragma unroll
        for (int i = 0; i < 4; i++)
            #pragma unroll
            for (int j = 0; j < 4; j++) {
                const int r0  = m0 + mo + i * 16 + g;
                const int col = n0g + no + j * 8 + tg * 2;
                size_t o0 = (size_t)r0 * Dn + col;
                size_t o1 = (size_t)(r0 + 8) * Dn + col;
                float2 x0 = *(const float2*)(Xres + o0);
                float2 x1 = *(const float2*)(Xres + o1);
                *(float2*)(g_res + o0) = make_float2(c[i][j][0] + x0.x, c[i][j][1] + x0.y);
                *(float2*)(g_res + o1) = make_float2(c[i][j][2] + x1.x, c[i][j][3] + x1.y);
            }
        return;
    }

    // mode 0 epilogue: split to bf16 hi/lo
    const int sel   = n0g >> 10;
    const int nbase = n0g & 1023;
    #pragma unroll
    for (int i = 0; i < 4; i++) {
        #pragma unroll
        for (int j = 0; j < 4; j++) {
            const int r0  = m0 + mo + i * 16 + g;
            const int col = nbase + no + j * 8 + tg * 2;
            float v0 = c[i][j][0], v1 = c[i][j][1], v2 = c[i][j][2], v3 = c[i][j][3];
            __nv_bfloat16 h0 = __float2bfloat16(v0), h1 = __float2bfloat16(v1);
            __nv_bfloat16 h2 = __float2bfloat16(v2), h3 = __float2bfloat16(v3);
            __nv_bfloat16 l0 = __float2bfloat16(v0 - __bfloat162float(h0));
            __nv_bfloat16 l1 = __float2bfloat16(v1 - __bfloat162float(h1));
            __nv_bfloat16 l2 = __float2bfloat16(v2 - __bfloat162float(h2));
            __nv_bfloat16 l3 = __float2bfloat16(v3 - __bfloat162float(h3));
            if (sel < 2) {
                __nv_bfloat16* HI = sel ? g_khi : g_qhi;
                __nv_bfloat16* LO = sel ? g_klo : g_qlo;
                size_t o0 = (size_t)r0 * Dn + col;
                size_t o1 = (size_t)(r0 + 8) * Dn + col;
                *(uint32_t*)(HI + o0) = pack_bf16(h0, h1);
                *(uint32_t*)(LO + o0) = pack_bf16(l0, l1);
                *(uint32_t*)(HI + o1) = pack_bf16(h2, h3);
                *(uint32_t*)(LO + o1) = pack_bf16(l2, l3);
            } else {
                const int b = r0 >> 10, s = r0 & 1023;
                const int h = col >> 6, d = col & 63;
                size_t o = ((size_t)((b * Hn + h) * DKn + d)) * Sn + s;
                g_vthi[o]          = h0;  g_vtlo[o]          = l0;
                g_vthi[o + Sn]     = h1;  g_vtlo[o + Sn]     = l1;
                g_vthi[o + 8]      = h2;  g_vtlo[o + 8]      = l2;
                g_vthi[o + Sn + 8] = h3;  g_vtlo[o + Sn + 8] = l3;
            }
        }
    }
}

// ======================== flash attention (HMMA, split-bf16) =================
// Block = (qtile 128, h, b). 8 warps x 16 q-rows. Bc=64 keys/iter, 16 iters.
// smem per stage: Khi[64][72], Klo, VThi[64][72], VTlo  (bf16, pad 72 vs bank conflicts)
#define KV_STRIDE 72
#define STAGE_ELEMS (4 * 64 * KV_STRIDE)          // 18432 bf16 per stage
#define ATTN_SMEM   (2 * STAGE_ELEMS * 2)         // 73728 bytes

__global__ __launch_bounds__(256, 1) void attn_flash_k(const int* __restrict__ mask)
{
    extern __shared__ __align__(16) __nv_bfloat16 smem[];
    const int tid = threadIdx.x, wid = tid >> 5, lane = tid & 31;
    const int g = lane >> 2, tg = lane & 3;
    const int q0 = blockIdx.x * 128;
    const int h  = blockIdx.y;
    const int b  = blockIdx.z;
    const size_t bS = (size_t)b * Sn;
    const int hh = h * DKn;
    const uint32_t sbase = smem_u32(smem);

    // ---- Q fragments (loaded once, kept in registers) ----
    const int qrow = q0 + wid * 16 + g;
    const __nv_bfloat16* qh = g_qhi + (bS + qrow) * Dn + hh;
    const __nv_bfloat16* ql = g_qlo + (bS + qrow) * Dn + hh;
    uint32_t aQh[4][4], aQl[4][4];
    #pragma unroll
    for (int kc = 0; kc < 4; kc++) {
        const int k2 = kc * 16 + 2 * tg;
        aQh[kc][0] = *(const uint32_t*)(qh + k2);
        aQh[kc][1] = *(const uint32_t*)(qh + 8 * Dn + k2);
        aQh[kc][2] = *(const uint32_t*)(qh + k2 + 8);
        aQh[kc][3] = *(const uint32_t*)(qh + 8 * Dn + k2 + 8);
        aQl[kc][0] = *(const uint32_t*)(ql + k2);
        aQl[kc][1] = *(const uint32_t*)(ql + 8 * Dn + k2);
        aQl[kc][2] = *(const uint32_t*)(ql + k2 + 8);
        aQl[kc][3] = *(const uint32_t*)(ql + 8 * Dn + k2 + 8);
    }

    float O[8][4];
    #pragma unroll
    for (int j = 0; j < 8; j++)
        #pragma unroll
        for (int r = 0; r < 4; r++) O[j][r] = 0.f;
    float mrow0 = -1e8f, mrow1 = -1e8f;
    float lrow0 = 0.f,   lrow1 = 0.f;

    const size_t vbase = (size_t)(b * Hn + h) * DKn;

    // staging helper (each thread: 2 x 16B per array)
    auto stage = [&](int it, int st) {
        const int t0 = it * 64;
        #pragma unroll
        for (int u = 0; u < 2; u++) {
            const int idx = tid + u * 256;
            const int row = idx >> 3, c16 = idx & 7;
            const uint32_t so = sbase + (uint32_t)(st * STAGE_ELEMS + row * KV_STRIDE + c16 * 8) * 2;
            const __nv_bfloat16* gkh = g_khi  + (bS + t0 + row) * Dn + hh + c16 * 8;
            const __nv_bfloat16* gkl = g_klo  + (bS + t0 + row) * Dn + hh + c16 * 8;
            const __nv_bfloat16* gvh = g_vthi + (vbase + row) * Sn + t0 + c16 * 8;
            const __nv_bfloat16* gvl = g_vtlo + (vbase + row) * Sn + t0 + c16 * 8;
            CP16(so,                        gkh);
            CP16(so + 64 * KV_STRIDE * 2,   gkl);
            CP16(so + 128 * KV_STRIDE * 2,  gvh);
            CP16(so + 192 * KV_STRIDE * 2,  gvl);
        }
    };

    stage(0, 0); CP_COMMIT();

    for (int it = 0; it < 16; it++) {
        const int st = it & 1;
        if (it < 15) { stage(it + 1, st ^ 1); CP_COMMIT(); CP_WAIT(1); }
        else         { CP_WAIT(0); }
        __syncthreads();

        const uint32_t skh = sbase + (uint32_t)(st * STAGE_ELEMS) * 2;
        const uint32_t skl = skh + 64 * KV_STRIDE * 2;
        const uint32_t svh = skh + 128 * KV_STRIDE * 2;
        const uint32_t svl = skh + 192 * KV_STRIDE * 2;

        // ---- scores: 3-pass split QK^T ----
        float c[8][4];
        #pragma unroll
        for (int j = 0; j < 8; j++)
            #pragma unroll
            for (int r = 0; r < 4; r++) c[j][r] = 0.f;

        #pragma unroll
        for (int kc = 0; kc < 4; kc++) {
            #pragma unroll
            for (int j = 0; j < 8; j++) {
                const uint32_t off = (uint32_t)((j * 8 + g) * KV_STRIDE + kc * 16 + 2 * tg) * 2;
                uint32_t bh[2], bl[2];
                bh[0] = lds32(skh + off); bh[1] = lds32(skh + off + 16);
                bl[0] = lds32(skl + off); bl[1] = lds32(skl + off + 16);
                mma16816(c[j], aQh[kc], bh);
                mma16816(c[j], aQh[kc], bl);
                mma16816(c[j], aQl[kc], bh);
            }
        }

        // ---- scale + mask ----
        const int t0 = it * 64;
        #pragma unroll
        for (int j = 0; j < 8; j++) {
            const int t = t0 + j * 8 + 2 * tg;
            int2 mm0 = *(const int2*)(mask + (bS + qrow) * Sn + t);
            int2 mm1 = *(const int2*)(mask + (bS + qrow + 8) * Sn + t);
            c[j][0] = mm0.x ? c[j][0] * 0.125f : -1e9f;
            c[j][1] = mm0.y ? c[j][1] * 0.125f : -1e9f;
            c[j][2] = mm1.x ? c[j][2] * 0.125f : -1e9f;
            c[j][3] = mm1.y ? c[j][3] * 0.125f : -1e9f;
        }

        // ---- online softmax ----
        float mx0 = -1e30f, mx1 = -1e30f;
        #pragma unroll
        for (int j = 0; j < 8; j++) {
            mx0 = fmaxf(mx0, fmaxf(c[j][0], c[j][1]));
            mx1 = fmaxf(mx1, fmaxf(c[j][2], c[j][3]));
        }
        mx0 = fmaxf(mx0, __shfl_xor_sync(0xffffffffu, mx0, 1));
        mx0 = fmaxf(mx0, __shfl_xor_sync(0xffffffffu, mx0, 2));
        mx1 = fmaxf(mx1, __shfl_xor_sync(0xffffffffu, mx1, 1));
        mx1 = fmaxf(mx1, __shfl_xor_sync(0xffffffffu, mx1, 2));

        const float mn0 = fmaxf(mrow0, mx0), mn1 = fmaxf(mrow1, mx1);
        const float al0 = __expf(mrow0 - mn0), al1 = __expf(mrow1 - mn1);
        mrow0 = mn0; mrow1 = mn1;

        float s0 = 0.f, s1 = 0.f;
        #pragma unroll
        for (int j = 0; j < 8; j++) {
            c[j][0] = __expf(c[j][0] - mn0); s0 += c[j][0];
            c[j][1] = __expf(c[j][1] - mn0); s0 += c[j][1];
            c[j][2] = __expf(c[j][2] - mn1); s1 += c[j][2];
            c[j][3] = __expf(c[j][3] - mn1); s1 += c[j][3];
        }
        lrow0 = lrow0 * al0 + s0;
        lrow1 = lrow1 * al1 + s1;
        #pragma unroll
        for (int j = 0; j < 8; j++) {
            O[j][0] *= al0; O[j][1] *= al0;
            O[j][2] *= al1; O[j][3] *= al1;
        }

        // ---- PV: P split to bf16 hi/lo, 3-pass against V^T ----
        #pragma unroll
        for (int kc = 0; kc < 4; kc++) {
            const float* p0 = c[2 * kc];
            const float* p1 = c[2 * kc + 1];
            __nv_bfloat16 h00 = __float2bfloat16(p0[0]), h01 = __float2bfloat16(p0[1]);
            __nv_bfloat16 h02 = __float2bfloat16(p0[2]), h03 = __float2bfloat16(p0[3]);
            __nv_bfloat16 h10 = __float2bfloat16(p1[0]), h11 = __float2bfloat16(p1[1]);
            __nv_bfloat16 h12 = __float2bfloat16(p1[2]), h13 = __float2bfloat16(p1[3]);
            uint32_t ah[4], al_[4];
            ah[0] = pack_bf16(h00, h01);
            ah[1] = pack_bf16(h02, h03);
            ah[2] = pack_bf16(h10, h11);
            ah[3] = pack_bf16(h12, h13);
            al_[0] = pack_bf16(__float2bfloat16(p0[0] - __bfloat162float(h00)),
                               __float2bfloat16(p0[1] - __bfloat162float(h01)));
            al_[1] = pack_bf16(__float2bfloat16(p0[2] - __bfloat162float(h02)),
                               __float2bfloat16(p0[3] - __bfloat162float(h03)));
            al_[2] = pack_bf16(__float2bfloat16(p1[0] - __bfloat162float(h10)),
                               __float2bfloat16(p1[1] - __bfloat162float(h11)));
            al_[3] = pack_bf16(__float2bfloat16(p1[2] - __bfloat162float(h12)),
                               __float2bfloat16(p1[3] - __bfloat162float(h13)));
            #pragma unroll
            for (int j = 0; j < 8; j++) {
                const uint32_t off = (uint32_t)((j * 8 + g) * KV_STRIDE + kc * 16 + 2 * tg) * 2;
                uint32_t bh[2], bl[2];
                bh[0] = lds32(svh + off); bh[1] = lds32(svh + off + 16);
                bl[0] = lds32(svl + off); bl[1] = lds32(svl + off + 16);
                mma16816(O[j], ah, bh);
                mma16816(O[j], ah, bl);
                mma16816(O[j], al_, bh);
            }
        }
        __syncthreads();
    }

    // ---- epilogue: normalize and write ctx bf16 hi/lo ----
    lrow0 += __shfl_xor_sync(0xffffffffu, lrow0, 1);
    lrow0 += __shfl_xor_sync(0xffffffffu, lrow0, 2);
    lrow1 += __shfl_xor_sync(0xffffffffu, lrow1, 1);
    lrow1 += __shfl_xor_sync(0xffffffffu, lrow1, 2);
    const float inv0 = 1.f / lrow0, inv1 = 1.f / lrow1;

    #pragma unroll
    for (int j = 0; j < 8; j++) {
        const int col = hh + j * 8 + 2 * tg;
        size_t o0 = (bS + qrow) * Dn + col;
        size_t o1 = (bS + qrow + 8) * Dn + col;
        float v0 = O[j][0] * inv0, v1 = O[j][1] * inv0;
        float v2 = O[j][2] * inv1, v3 = O[j][3] * inv1;
        __nv_bfloat16 h0 = __float2bfloat16(v0), h1 = __float2bfloat16(v1);
        __nv_bfloat16 h2 = __float2bfloat16(v2), h3 = __float2bfloat16(v3);
        *(uint32_t*)(g_chi + o0) = pack_bf16(h0, h1);
        *(uint32_t*)(g_clo + o0) = pack_bf16(__float2bfloat16(v0 - __bfloat162float(h0)),
                                             __float2bfloat16(v1 - __bfloat162float(h1)));
        *(uint32_t*)(g_chi + o1) = pack_bf16(h2, h3);
        *(uint32_t*)(g_clo + o1) = pack_bf16(__float2bfloat16(v2 - __bfloat162float(h2)),
                                             __float2bfloat16(v3 - __bfloat162float(h3)));
    }
}

// ======================== LayerNorm ==========================================
__global__ __launch_bounds__(256) void ln_partial_k()
{
    const int blk = blockIdx.x;
    const int b   = blk / 32;
    const int seg = blk % 32;
    const float* base = g_res + (size_t)b * Sn * Dn + (size_t)seg * 32768;

    float s = 0.f, s2 = 0.f;
    for (int i = threadIdx.x; i < 32768; i += 256) {
        float v = base[i];
        s += v;
        s2 += v * v;
    }
    __shared__ double sh1[256], sh2[256];
    sh1[threadIdx.x] = (double)s;
    sh2[threadIdx.x] = (double)s2;
    __syncthreads();
    for (int o = 128; o > 0; o >>= 1) {
        if (threadIdx.x < o) {
            sh1[threadIdx.x] += sh1[threadIdx.x + o];
            sh2[threadIdx.x] += sh2[threadIdx.x + o];
        }
        __syncthreads();
    }
    if (threadIdx.x == 0) {
        g_part[blk * 2 + 0] = sh1[0];
        g_part[blk * 2 + 1] = sh2[0];
    }
}

__global__ void ln_finish_k()
{
    const int b = blockIdx.x;
    const int l = threadIdx.x;
    __shared__ double sh[64];
    sh[l]      = g_part[(b * 32 + l) * 2 + 0];
    sh[32 + l] = g_part[(b * 32 + l) * 2 + 1];
    __syncthreads();
    if (l == 0) {
        double S = 0.0, S2 = 0.0;
        for (int i = 0; i < 32; i++) { S += sh[i]; S2 += sh[32 + i]; }
        const double N = (double)Sn * (double)Dn;
        double mean = S / N;
        double var  = S2 / N - mean * mean;
        g_stats[b * 2 + 0] = (float)mean;
        g_stats[b * 2 + 1] = (float)(1.0 / sqrt(var + 1e-5));
    }
}

__global__ __launch_bounds__(256) void ln_norm_k(float* __restrict__ out)
{
    const int idx = blockIdx.x * 256 + threadIdx.x;
    const size_t i4 = (size_t)idx * 4;
    const int b = (int)(i4 >> 20);
    const float mean = g_stats[b * 2 + 0];
    const float istd = g_stats[b * 2 + 1];
    float4 v = *(const float4*)&g_res[i4];
    v.x = (v.x - mean) * istd;
    v.y = (v.y - mean) * istd;
    v.z = (v.z - mean) * istd;
    v.w = (v.w - mean) * istd;
    *(float4*)&out[i4] = v;
}

// =============================================================================
extern "C" void kernel_launch(void* const* d_in, const int* in_sizes, int n_in,
                              void* d_out, int out_size)
{
    const int*   mask = (const int*)  d_in[0];
    const float* x    = (const float*)d_in[1];
    const float* wq   = (const float*)d_in[2];
    const float* wk   = (const float*)d_in[3];
    const float* wv   = (const float*)d_in[4];
    const float* wo   = (const float*)d_in[5];
    float* out = (float*)d_out;

    cudaFuncSetAttribute(attn_flash_k, cudaFuncAttributeMaxDynamicSharedMemorySize, ATTN_SMEM);

    // 0) bf16 split conversions
    cvt_split_k<<<(Bn * Sn * Dn) / (256 * 4), 256>>>(x);
    cvt_wqkv_k<<<(3 * Dn * Dn) / 256, 256>>>(wq, wk, wv);
    cvt_wo_k<<<dim3(Dn / 32, Dn / 32), dim3(32, 8)>>>(wo);

    // 1) fused QKV projection -> q/k splits + transposed V splits
    gemm_mma_k<<<dim3(24, 64), 256>>>(nullptr, 0);

    // 2) flash attention -> ctx splits
    attn_flash_k<<<dim3(Sn / 128, Hn, Bn), 256, ATTN_SMEM>>>(mask);

    // 3) output projection + residual
    gemm_mma_k<<<dim3(8, 64), 256>>>(x, 1);

    // 4) layernorm over (S, D) per batch
    ln_partial_k<<<Bn * 32, 256>>>();
    ln_finish_k<<<Bn, 32>>>();
    ln_norm_k<<<(Bn * Sn * Dn) / (256 * 4), 256>>>(out);
}